// round 13
// baseline (speedup 1.0000x reference)
#include <cuda_runtime.h>
#include <cuda_bf16.h>
#include <math.h>
#include <stdint.h>

// ---------------- problem constants ----------------
#define Bn 16
#define Tn 2048
#define Dn 1024
#define Cn 512
#define MTILE 64                   // rows per CTA
#define KC 32                      // K per chunk
#define NCH (Dn / KC)              // 32 chunks
#define NBLK ((Bn * Tn) / MTILE)   // 512 CTAs
#define NT 256                     // threads per CTA (8 warps)
#define RSB 80                     // smem row stride in BYTES — ldmatrix conflict-free

// ---------------- smem layout (bytes) ----------------
#define SM_AH 0
#define SM_AL (MTILE * RSB)            // 5120
#define SM_BH (2 * MTILE * RSB)        // 10240
#define SM_BL (SM_BH + Cn * RSB)       // 51200
#define STAGE (SM_BL + Cn * RSB)       // 92160
#define SM_TOTAL (2 * STAGE)           // 184320

// epilogue aliases (float indices)
#define EP_CS  0      // colsum[512]
#define EP_M   512    // sm_m[64][4]
#define EP_S   768    // sm_s[64][4]
#define EP_MM  1024   // sm_M[64]
#define EP_INV 1088   // sm_inv[64]

// ---------------- device scratch ----------------
__device__ __align__(256) __nv_bfloat16 g_Whi[Cn * Dn];
__device__ __align__(256) __nv_bfloat16 g_Wlo[Cn * Dn];
__device__ float g_colsum[NBLK * Cn];
__device__ float g_lterm[Bn];

// ---------------- ptx helpers ----------------
__device__ __forceinline__ uint32_t s2u(const void* p) {
    uint32_t a;
    asm("{ .reg .u64 t; cvta.to.shared.u64 t, %1; cvt.u32.u64 %0, t; }" : "=r"(a) : "l"(p));
    return a;
}
__device__ __forceinline__ void cpa16(uint32_t dst, const void* src) {
    asm volatile("cp.async.cg.shared.global [%0], [%1], 16;" :: "r"(dst), "l"(src));
}
__device__ __forceinline__ void ldsm4(uint32_t addr, uint32_t* r) {
    asm volatile("ldmatrix.sync.aligned.m8n8.x4.shared.b16 {%0,%1,%2,%3}, [%4];"
                 : "=r"(r[0]), "=r"(r[1]), "=r"(r[2]), "=r"(r[3]) : "r"(addr));
}
__device__ __forceinline__ void mma16816(float* c, const uint32_t* a, const uint32_t* b) {
    asm volatile("mma.sync.aligned.m16n8k16.row.col.f32.bf16.bf16.f32 "
                 "{%0,%1,%2,%3}, {%4,%5,%6,%7}, {%8,%9}, {%0,%1,%2,%3};"
                 : "+f"(c[0]), "+f"(c[1]), "+f"(c[2]), "+f"(c[3])
                 : "r"(a[0]), "r"(a[1]), "r"(a[2]), "r"(a[3]), "r"(b[0]), "r"(b[1]));
}

// ---------------------------------------------------------------------------
// Kernel 0: split W (fp32) into bf16 hi/lo
// ---------------------------------------------------------------------------
__global__ void __launch_bounds__(512)
wsplit_kernel(const float* __restrict__ W)
{
    int i = blockIdx.x * 512 + threadIdx.x;
    float x = W[i];
    __nv_bfloat16 h = __float2bfloat16(x);
    g_Whi[i] = h;
    g_Wlo[i] = __float2bfloat16(x - __bfloat162float(h));
}

// ---------------------------------------------------------------------------
// Kernel 1: bf16 3-split mma.sync GEMM + softmax epilogue + colsum
// CTA: 64 rows x 512 cols. 8 warps, warp tile 32x128 (2 M-tiles x 16 N-tiles).
// 256 threads -> 255-reg ceiling: full fragment prefetch, dense MMA issue.
// ---------------------------------------------------------------------------
__global__ void __launch_bounds__(NT, 1)
cam_mma_kernel(const float* __restrict__ feat,
               float* __restrict__ out_soft, float* __restrict__ out_raw)
{
    extern __shared__ char smem[];
    float* smf = (float*)smem;
    const uint32_t sb = s2u(smem);
    const int tid  = threadIdx.x;
    const int w    = tid >> 5, lane = tid & 31;
    const int Rbase = blockIdx.x * MTILE;
    const int mrow0 = (w & 1) * 32;          // 2 M-groups
    const int n0    = (w >> 1) * 128;        // 4 N-groups of 128

    float acc[2][16][4];
#pragma unroll
    for (int mt = 0; mt < 2; mt++)
#pragma unroll
        for (int nt = 0; nt < 16; nt++)
#pragma unroll
            for (int k = 0; k < 4; k++) acc[mt][nt][k] = 0.f;

    // ---- load helpers ----
    const int ar = tid >> 2, aq2 = (tid & 3) * 2;  // A row 0..63, 2 float4-groups
    float4 areg[2];
    auto LDGA = [&](int k0) {
        const float* p = &feat[(size_t)(Rbase + ar) * Dn + k0 + aq2 * 4];
        areg[0] = *(const float4*)p;
        areg[1] = *(const float4*)(p + 4);
    };
    auto STSA = [&](int buf) {
#pragma unroll
        for (int q = 0; q < 2; q++) {
            float4 v = areg[q];
            __nv_bfloat16 h0 = __float2bfloat16(v.x), h1 = __float2bfloat16(v.y);
            __nv_bfloat16 h2 = __float2bfloat16(v.z), h3 = __float2bfloat16(v.w);
            __nv_bfloat16 l0 = __float2bfloat16(v.x - __bfloat162float(h0));
            __nv_bfloat16 l1 = __float2bfloat16(v.y - __bfloat162float(h1));
            __nv_bfloat16 l2 = __float2bfloat16(v.z - __bfloat162float(h2));
            __nv_bfloat16 l3 = __float2bfloat16(v.w - __bfloat162float(h3));
            uint2 hv, lv;
            hv.x = (uint32_t)__bfloat16_as_ushort(h0) | ((uint32_t)__bfloat16_as_ushort(h1) << 16);
            hv.y = (uint32_t)__bfloat16_as_ushort(h2) | ((uint32_t)__bfloat16_as_ushort(h3) << 16);
            lv.x = (uint32_t)__bfloat16_as_ushort(l0) | ((uint32_t)__bfloat16_as_ushort(l1) << 16);
            lv.y = (uint32_t)__bfloat16_as_ushort(l2) | ((uint32_t)__bfloat16_as_ushort(l3) << 16);
            char* base = smem + buf * STAGE + ar * RSB + (aq2 + q) * 8;
            *(uint2*)(base + SM_AH) = hv;
            *(uint2*)(base + SM_AL) = lv;
        }
    };
    auto LDB = [&](int buf, int k0) {
#pragma unroll
        for (int i = 0; i < 8; i++) {
            int g = tid + i * NT;              // 0..2047
            int row = g >> 2, grp = g & 3;
            uint32_t dst = sb + buf * STAGE + row * RSB + grp * 16;
            const __nv_bfloat16* sh = g_Whi + (size_t)row * Dn + k0 + grp * 8;
            const __nv_bfloat16* sl = g_Wlo + (size_t)row * Dn + k0 + grp * 8;
            cpa16(dst + SM_BH, sh);
            cpa16(dst + SM_BL, sl);
        }
        asm volatile("cp.async.commit_group;" ::: "memory");
    };

    // ldmatrix lane addressing
    const int alr = lane & 15;                       // A row-within-16
    const int akb = ((lane >> 4) & 1) * 16;          // A k-half byte
    const int brow = ((lane >> 4) & 1) * 8 + (lane & 7); // B row-within-16
    const int bkb = ((lane >> 3) & 1) * 16;          // B k-half byte

    auto COMPUTE = [&](int buf) {
        const uint32_t st = sb + buf * STAGE;
#pragma unroll
        for (int ks = 0; ks < 2; ks++) {
            uint32_t ah[2][4], al[2][4];
#pragma unroll
            for (int mt = 0; mt < 2; mt++) {
                uint32_t arow = (mrow0 + mt * 16 + alr) * RSB + ks * 32 + akb;
                ldsm4(st + SM_AH + arow, ah[mt]);
                ldsm4(st + SM_AL + arow, al[mt]);
            }
            // double-buffered B fragments: prefetch bt+1 while doing MMAs for bt
            uint32_t bh[2][4], bl[2][4];
            {
                uint32_t boff = (n0 + brow) * RSB + ks * 32 + bkb;
                ldsm4(st + SM_BH + boff, bh[0]);
                ldsm4(st + SM_BL + boff, bl[0]);
            }
#pragma unroll
            for (int bt = 0; bt < 8; bt++) {
                int cur = bt & 1, nxt = cur ^ 1;
                if (bt + 1 < 8) {
                    uint32_t boff = (n0 + (bt + 1) * 16 + brow) * RSB + ks * 32 + bkb;
                    ldsm4(st + SM_BH + boff, bh[nxt]);
                    ldsm4(st + SM_BL + boff, bl[nxt]);
                }
#pragma unroll
                for (int mt = 0; mt < 2; mt++)
#pragma unroll
                    for (int n2 = 0; n2 < 2; n2++) {
                        float* C = acc[mt][bt * 2 + n2];
                        mma16816(C, ah[mt], bh[cur] + n2 * 2);
                        mma16816(C, ah[mt], bl[cur] + n2 * 2);
                        mma16816(C, al[mt], bh[cur] + n2 * 2);
                    }
            }
        }
    };

    // ---- prologue ----
    LDGA(0);
    LDB(0, 0);
    STSA(0);
    asm volatile("cp.async.wait_group 0;" ::: "memory");
    __syncthreads();

    // ---- mainloop ----
#pragma unroll 1
    for (int c = 0; c < NCH; c++) {
        if (c + 1 < NCH) {
            LDGA((c + 1) * KC);
            LDB((c + 1) & 1, (c + 1) * KC);
        }
        COMPUTE(c & 1);
        if (c + 1 < NCH) {
            STSA((c + 1) & 1);
            asm volatile("cp.async.wait_group 0;" ::: "memory");
        }
        __syncthreads();
    }

    // ---------------- epilogue ----------------
    // thread rows: mrow0 + mt*16 + h*8 + (lane>>2);  cols: n0 + nt*8 + 2*(lane&3)+{0,1}
    smf[EP_CS + tid] = 0.f;
    smf[EP_CS + tid + NT] = 0.f;

    // row max
    float rm[2][2];
#pragma unroll
    for (int mt = 0; mt < 2; mt++)
#pragma unroll
        for (int h = 0; h < 2; h++) {
            float m = -INFINITY;
#pragma unroll
            for (int nt = 0; nt < 16; nt++)
                m = fmaxf(m, fmaxf(acc[mt][nt][h * 2], acc[mt][nt][h * 2 + 1]));
            m = fmaxf(m, __shfl_xor_sync(0xffffffffu, m, 1));
            m = fmaxf(m, __shfl_xor_sync(0xffffffffu, m, 2));
            rm[mt][h] = m;
        }
    if ((lane & 3) == 0)
#pragma unroll
        for (int mt = 0; mt < 2; mt++)
#pragma unroll
            for (int h = 0; h < 2; h++) {
                int rl = mrow0 + mt * 16 + h * 8 + (lane >> 2);
                smf[EP_M + rl * 4 + (w >> 1)] = rm[mt][h];
            }
    __syncthreads();
    if (tid < 64) {
        float M = smf[EP_M + tid * 4];
#pragma unroll
        for (int i = 1; i < 4; i++) M = fmaxf(M, smf[EP_M + tid * 4 + i]);
        smf[EP_MM + tid] = M;
    }
    __syncthreads();

    // exp-sum
    float Mrow[2][2];
#pragma unroll
    for (int mt = 0; mt < 2; mt++)
#pragma unroll
        for (int h = 0; h < 2; h++) {
            int rl = mrow0 + mt * 16 + h * 8 + (lane >> 2);
            Mrow[mt][h] = smf[EP_MM + rl];
            float s = 0.f;
#pragma unroll
            for (int nt = 0; nt < 16; nt++) {
                s += __expf(acc[mt][nt][h * 2]     - Mrow[mt][h]);
                s += __expf(acc[mt][nt][h * 2 + 1] - Mrow[mt][h]);
            }
            s += __shfl_xor_sync(0xffffffffu, s, 1);
            s += __shfl_xor_sync(0xffffffffu, s, 2);
            if ((lane & 3) == 0) smf[EP_S + rl * 4 + (w >> 1)] = s;
        }
    __syncthreads();
    if (tid < 64) {
        float S = 0.f;
#pragma unroll
        for (int i = 0; i < 4; i++) S += smf[EP_S + tid * 4 + i];
        smf[EP_INV + tid] = 1.0f / S;
    }
    __syncthreads();

    // store softmax (both outputs) + colsum
    float inv[2][2];
#pragma unroll
    for (int mt = 0; mt < 2; mt++)
#pragma unroll
        for (int h = 0; h < 2; h++) {
            int rl = mrow0 + mt * 16 + h * 8 + (lane >> 2);
            inv[mt][h] = smf[EP_INV + rl];
        }
#pragma unroll
    for (int mt = 0; mt < 2; mt++)
#pragma unroll
        for (int h = 0; h < 2; h++) {
            int rl = mrow0 + mt * 16 + h * 8 + (lane >> 2);
            size_t gbase = (size_t)(Rbase + rl) * Cn + n0 + 2 * (lane & 3);
#pragma unroll
            for (int nt = 0; nt < 16; nt++) {
                float2 o;
                o.x = __expf(acc[mt][nt][h * 2]     - Mrow[mt][h]) * inv[mt][h];
                o.y = __expf(acc[mt][nt][h * 2 + 1] - Mrow[mt][h]) * inv[mt][h];
                __stcs((float2*)&out_soft[gbase + nt * 8], o);
                __stcs((float2*)&out_raw [gbase + nt * 8], o);
            }
        }
    // colsum over this warp's 32 rows
#pragma unroll
    for (int nt = 0; nt < 16; nt++)
#pragma unroll
        for (int cc = 0; cc < 2; cc++) {
            float s = 0.f;
#pragma unroll
            for (int mt = 0; mt < 2; mt++)
#pragma unroll
                for (int h = 0; h < 2; h++) s += acc[mt][nt][h * 2 + cc];
            s += __shfl_xor_sync(0xffffffffu, s, 4);
            s += __shfl_xor_sync(0xffffffffu, s, 8);
            s += __shfl_xor_sync(0xffffffffu, s, 16);
            if (lane < 4)
                atomicAdd(&smf[EP_CS + n0 + nt * 8 + 2 * (lane & 3) + cc], s);
        }
    __syncthreads();
    __stcs(&g_colsum[(size_t)blockIdx.x * Cn + tid], smf[EP_CS + tid]);
    __stcs(&g_colsum[(size_t)blockIdx.x * Cn + tid + NT], smf[EP_CS + tid + NT]);
}

// ---------------------------------------------------------------------------
// Kernel 2: logits = mean_t(cam) + bias; per-batch log-softmax CE term
// ---------------------------------------------------------------------------
__global__ void __launch_bounds__(Cn)
logits_kernel(const float* __restrict__ bias, const int* __restrict__ labels,
              float* __restrict__ out_logits)
{
    __shared__ float sm_log[Cn];
    __shared__ float redm[16], reds[16];
    __shared__ float sMax;

    const int b = blockIdx.x;
    const int c = threadIdx.x;
    const int lane = c & 31, wid = c >> 5;

    float s = 0.f;
    const int base = b * (Tn / MTILE);   // 32 tiles per batch
#pragma unroll 4
    for (int mb = 0; mb < Tn / MTILE; mb++) s += g_colsum[(size_t)(base + mb) * Cn + c];
    float logit = s * (1.0f / Tn) + bias[c];
    out_logits[b * Cn + c] = logit;
    sm_log[c] = logit;

    float m = logit;
#pragma unroll
    for (int off = 16; off > 0; off >>= 1)
        m = fmaxf(m, __shfl_xor_sync(0xffffffffu, m, off));
    if (lane == 0) redm[wid] = m;
    __syncthreads();
    if (c == 0) {
        float mm = redm[0];
        for (int i = 1; i < 16; i++) mm = fmaxf(mm, redm[i]);
        sMax = mm;
    }
    __syncthreads();

    float e = expf(logit - sMax);
#pragma unroll
    for (int off = 16; off > 0; off >>= 1)
        e += __shfl_xor_sync(0xffffffffu, e, off);
    if (lane == 0) reds[wid] = e;
    __syncthreads();
    if (c == 0) {
        float ss = 0.f;
        for (int i = 0; i < 16; i++) ss += reds[i];
        int lab = labels[b];
        g_lterm[b] = -(sm_log[lab] - sMax - logf(ss));
    }
}

__global__ void loss_kernel(float* __restrict__ out_loss)
{
    if (threadIdx.x == 0) {
        float s = 0.f;
        for (int b = 0; b < Bn; b++) s += g_lterm[b];
        out_loss[0] = s * (1.0f / Bn);
    }
}

// ---------------------------------------------------------------------------
extern "C" void kernel_launch(void* const* d_in, const int* in_sizes, int n_in,
                              void* d_out, int out_size)
{
    const float* feat   = (const float*)d_in[0];
    const int*   labels = (const int*)d_in[1];     // int32 (JAX x64 disabled)
    const float* W      = (const float*)d_in[2];
    const float* bias   = (const float*)d_in[3];

    float* out        = (float*)d_out;
    float* out_soft   = out;
    float* out_raw    = out + (size_t)Bn * Tn * Cn;
    float* out_logits = out + 2 * (size_t)Bn * Tn * Cn;
    float* out_loss   = out_logits + Bn * Cn;

    cudaFuncSetAttribute(cam_mma_kernel, cudaFuncAttributeMaxDynamicSharedMemorySize, SM_TOTAL);

    wsplit_kernel<<<(Cn * Dn) / 512, 512>>>(W);
    cam_mma_kernel<<<NBLK, NT, SM_TOTAL>>>(feat, out_soft, out_raw);
    logits_kernel<<<Bn, Cn>>>(bias, labels, out_logits);
    loss_kernel<<<1, 32>>>(out_loss);
}